// round 7
// baseline (speedup 1.0000x reference)
#include <cuda_runtime.h>
#include <cuda_fp16.h>
#include <cstdint>

// ============================================================================
// FastTSAGEConv fused kernel for GB300 (plain sm_103 PTX feature set):
// legacy HMMA mma.sync.m16n8k16 fp16 (fp32 accum), 1-pass.
//
//   hn[e]  = (sum_{j=ss..me} src_feat[j]) / (deg[e]+1),  ss = me - deg + 1
//   out[e] = [dst_feat[e] | hn[e]] @ [W_self; W_neigh] + (b_self + b_neigh)
//
// R6 -> R7: the per-edge segment sum walked a DEPENDENT gmem chain (latency-
// bound; occupancy scaling flattened). Now: cooperatively stage src rows
// [m0-8, m0+64) into smem (72 rows, 9 independent coalesced float4 loads per
// thread), then segment sums read smem (29-cyc LDS). Edges reaching further
// back (~2-4%) use the old __ldg fallback. Out-stage aliases the src buffer
// (disjoint phases) -> 70.7 KB smem/CTA -> 3 CTAs/SM, reg cap 84 (no spills).
// ============================================================================

#define TILE_M     64
#define NTHREADS   256
#define OCC        3
#define ROWS_BACK  8
#define SRC_ROWS   (TILE_M + ROWS_BACK)         // 72

// ---- smem layout ----
// [0, 36864)        : src_buf fp32 [72][128]  (aliased by out-stage later)
// [36864, 70656)    : A fp16 [64][528B]
static constexpr int SMEM_SRC   = 0;
static constexpr int SMEM_A_OFF = SRC_ROWS * 128 * 4;        // 36864
static constexpr int A_STRIDE_B = 528;
static constexpr int STG_STRIDE = 136;          // floats per out-stage row (pad 8)
static constexpr int SMEM_TOTAL = SMEM_A_OFF + TILE_M * A_STRIDE_B;  // 70656

// Pre-packed B fragments: [kstep 0..15][nblock 0..15][lane 0..31] x 2 u32
// (64 KB, stays hot in L1 across the whole kernel)
__device__ uint2 g_bfrag[16 * 16 * 32];
// dtype flag for dst_max_eid: 1 if int64, 0 if int32
__device__ int g_eid_is64;

// ============================ helpers ===================================
__device__ __forceinline__ uint32_t smem_to_u32(const void* smem_ptr) {
    uint32_t addr;
    asm("{ .reg .u64 tmp; cvta.to.shared.u64 tmp, %1; cvt.u32.u64 %0, tmp; }"
        : "=r"(addr) : "l"(smem_ptr));
    return addr;
}

__device__ __forceinline__ uint32_t f22u(float a, float b) {
    __half2 h = __floats2half2_rn(a, b);
    return *reinterpret_cast<uint32_t*>(&h);
}

__device__ __forceinline__ void mma16816(float* c, const uint32_t* a,
                                         uint32_t b0, uint32_t b1) {
    asm volatile(
        "mma.sync.aligned.m16n8k16.row.col.f32.f16.f16.f32 "
        "{%0,%1,%2,%3}, {%4,%5,%6,%7}, {%8,%9}, {%0,%1,%2,%3};\n"
        : "+f"(c[0]), "+f"(c[1]), "+f"(c[2]), "+f"(c[3])
        : "r"(a[0]), "r"(a[1]), "r"(a[2]), "r"(a[3]), "r"(b0), "r"(b1));
}

// ============================================================================
// Prep kernel (also hosts the dtype probe in block 0): pack
// B = [W_self; W_neigh] (256 x 128 f32) into fp16 MMA fragment layout.
// For kstep s (k0=16s), nblock nb (n0=8nb), lane l:
//   kA = 16s + (l%4)*2,  n = 8nb + l/4
//   reg0 = half2( B[kA][n],   B[kA+1][n] )
//   reg1 = half2( B[kA+8][n], B[kA+9][n] )
// Probe: view dst_max_eid as int64 at elements [E/4, E/4+256) (word indices
// < E under either dtype). True int64 (values in [0,E)) => all high words 0;
// int32 data there holds values ~E/2 != 0.
// ============================================================================
__global__ void prep_w_kernel(const float* __restrict__ Wself,
                              const float* __restrict__ Wneigh,
                              const unsigned* __restrict__ dme_words, int E) {
    if (blockIdx.x == 0) {
        __shared__ int nz;
        if (threadIdx.x == 0) nz = 0;
        __syncthreads();
        int i = E / 4 + threadIdx.x;
        unsigned hi = dme_words[2 * i + 1];
        if (hi != 0u) atomicAdd(&nz, 1);
        __syncthreads();
        if (threadIdx.x == 0) g_eid_is64 = (nz == 0) ? 1 : 0;
    }
    int idx = blockIdx.x * blockDim.x + threadIdx.x;    // 0..8191
    if (idx >= 16 * 16 * 32) return;
    int lane = idx & 31;
    int nb   = (idx >> 5) & 15;
    int s    = idx >> 9;
    int k0 = s * 16 + (lane & 3) * 2;
    int n  = nb * 8 + (lane >> 2);

    auto wc = [&](int k) -> float {
        return (k < 128) ? Wself[k * 128 + n] : Wneigh[(k - 128) * 128 + n];
    };
    uint2 v;
    v.x = f22u(wc(k0),     wc(k0 + 1));
    v.y = f22u(wc(k0 + 8), wc(k0 + 9));
    g_bfrag[idx] = v;
}

// ============================================================================
// Main persistent kernel — 3 CTAs/SM
// ============================================================================
__global__ void __launch_bounds__(NTHREADS, OCC)
fused_tsage_kernel(const float* __restrict__ src_feat,
                   const float* __restrict__ dst_feat,
                   const int*   __restrict__ dst_max_eid,
                   const float* __restrict__ dst_deg,
                   const float* __restrict__ b_self,
                   const float* __restrict__ b_neigh,
                   float* __restrict__ out,
                   int E, int num_tiles) {
    extern __shared__ char smem[];
    const uint32_t smem_base = smem_to_u32(smem);
    const int tid = threadIdx.x;
    const int wid = tid >> 5;
    const int lid = tid & 31;
    const int wm  = wid & 3;        // M-warp 0..3  (rows wm*16 .. +15)
    const int wn  = wid >> 2;       // N-warp 0..1  (cols wn*64 .. +63)
    const int is64 = g_eid_is64;
    const long long* dme64 = reinterpret_cast<const long long*>(dst_max_eid);

    // per-lane bias for the coalesced epilogue (cols 4*lid..4*lid+3)
    const float bia0 = b_self[4 * lid + 0] + b_neigh[4 * lid + 0];
    const float bia1 = b_self[4 * lid + 1] + b_neigh[4 * lid + 1];
    const float bia2 = b_self[4 * lid + 2] + b_neigh[4 * lid + 2];
    const float bia3 = b_self[4 * lid + 3] + b_neigh[4 * lid + 3];

    // ldmatrix per-lane address pieces (A tile, 528B row stride)
    const int ldsm_row = (lid & 7) + ((lid >> 3) & 1) * 8;   // row within 16
    const int ldsm_k16 = (lid >> 4) * 16;                    // +16B for k 8..15
    const uint32_t a_base = smem_base + SMEM_A_OFF;

    float* src_buf = reinterpret_cast<float*>(smem);         // [72][128] fp32
    float* stage   = reinterpret_cast<float*>(smem);         // aliases src_buf
    // per-warp B fragment pointer (this warp's wn half), L1-resident
    const uint2* __restrict__ bfrag_w = g_bfrag + (size_t)(wn * 8) * 32 + lid;

    for (int t = blockIdx.x; t < num_tiles; t += gridDim.x) {
        const int m0 = t * TILE_M;
        const int lo = m0 - ROWS_BACK;

        // ========= phase 1: cooperative stage of src rows [lo, m0+64) =======
        // 72 rows * 32 float4 = 2304 slots, 9 per thread, all independent.
#pragma unroll
        for (int i = 0; i < 9; i++) {
            const int flat = i * NTHREADS + tid;
            const int row  = flat >> 5;          // 0..71
            const int col  = (flat & 31) * 4;
            const int jg   = lo + row;
            if (jg >= 0 && jg < E) {
                float4 v = __ldg(reinterpret_cast<const float4*>(
                    src_feat + (size_t)jg * 128 + col));
                *reinterpret_cast<float4*>(src_buf + row * 128 + col) = v;
            }
        }
        // ========= phase 1b: dst_feat -> A cols 0..127 (independent loads) ==
#pragma unroll 4
        for (int rr = 0; rr < 8; rr++) {
            const int r = wid * 8 + rr;
            const int e = m0 + r;
            if (e < E) {
                float4 dv = __ldg(reinterpret_cast<const float4*>(
                    dst_feat + (size_t)e * 128 + 4 * lid));
                uint32_t addr = a_base + (uint32_t)r * A_STRIDE_B + 8u * lid;
                uint32_t d01 = f22u(dv.x, dv.y);
                uint32_t d23 = f22u(dv.z, dv.w);
                asm volatile("st.shared.v2.b32 [%0], {%1,%2};"
                             :: "r"(addr), "r"(d01), "r"(d23) : "memory");
            }
        }
        __syncthreads();

        // ========= phase 2: segment sums from smem -> A cols 128..255 =======
#pragma unroll 1
        for (int rr = 0; rr < 8; rr++) {
            const int r = wid * 8 + rr;
            const int e = m0 + r;
            if (e < E) {
                int me = is64 ? (int)dme64[e] : dst_max_eid[e];
                const float degf = dst_deg[e];
                if (me >= E) me = E - 1;           // bounded under any mis-parse
                if (me < 0)  me = 0;
                int ss = me - (int)degf + 1;
                if (ss < 0) ss = 0;

                float ax = 0.f, ay = 0.f, az = 0.f, aw = 0.f;
                if (ss >= lo) {
                    // fast path: all rows staged in smem
                    const float* p = src_buf + (size_t)(ss - lo) * 128 + 4 * lid;
                    const int cnt = me - ss + 1;
                    int j = 0;
#pragma unroll 1
                    for (; j + 2 <= cnt; j += 2) {
                        float4 v0 = *reinterpret_cast<const float4*>(p + (size_t)(j) * 128);
                        float4 v1 = *reinterpret_cast<const float4*>(p + (size_t)(j + 1) * 128);
                        ax += v0.x + v1.x; ay += v0.y + v1.y;
                        az += v0.z + v1.z; aw += v0.w + v1.w;
                    }
                    if (j < cnt) {
                        float4 v0 = *reinterpret_cast<const float4*>(p + (size_t)j * 128);
                        ax += v0.x; ay += v0.y; az += v0.z; aw += v0.w;
                    }
                } else {
                    // rare fallback: segment reaches further back than staged
                    const float4* sp4 = reinterpret_cast<const float4*>(
                        src_feat + (size_t)ss * 128 + 4 * lid);
                    const int cnt = me - ss + 1;
#pragma unroll 1
                    for (int j = 0; j < cnt; j++) {
                        float4 v0 = __ldg(sp4 + (size_t)j * 32);
                        ax += v0.x; ay += v0.y; az += v0.z; aw += v0.w;
                    }
                }
                const float inv = 1.0f / (degf + 1.0f);
                uint32_t addr = a_base + (uint32_t)r * A_STRIDE_B + 256u + 8u * lid;
                uint32_t h01 = f22u(ax * inv, ay * inv);
                uint32_t h23 = f22u(az * inv, aw * inv);
                asm volatile("st.shared.v2.b32 [%0], {%1,%2};"
                             :: "r"(addr), "r"(h01), "r"(h23) : "memory");
            }
        }
        __syncthreads();

        // ========= MMA phase: warp tile 16x64, K=256 ========================
        float acc[8][4];
#pragma unroll
        for (int nb = 0; nb < 8; nb++)
#pragma unroll
            for (int q = 0; q < 4; q++) acc[nb][q] = 0.f;

#pragma unroll 4
        for (int s = 0; s < 16; s++) {
            uint32_t a[4];
            {
                const int row0 = wm * 16;
                uint32_t addr = a_base + (uint32_t)(row0 + ldsm_row) * A_STRIDE_B
                              + (uint32_t)ldsm_k16 + (uint32_t)s * 32u;
                asm volatile(
                    "ldmatrix.sync.aligned.m8n8.x4.shared.b16 {%0,%1,%2,%3}, [%4];"
                    : "=r"(a[0]), "=r"(a[1]), "=r"(a[2]), "=r"(a[3])
                    : "r"(addr));
            }
            const uint2* bp = bfrag_w + (size_t)(s * 16) * 32;
#pragma unroll
            for (int nb = 0; nb < 8; nb++) {
                uint2 b = __ldg(bp + (size_t)nb * 32);
                mma16816(acc[nb], a, b.x, b.y);
            }
        }
        __syncthreads();   // A reads done; stage (aliasing src_buf) free to write

        // ========= epilogue: regs -> fp32 stage =============================
#pragma unroll
        for (int nb = 0; nb < 8; nb++) {
            const int r0 = wm * 16 + (lid >> 2);
            const int n  = wn * 64 + nb * 8 + (lid & 3) * 2;
            float* p0 = stage + r0 * STG_STRIDE + n;
            p0[0] = acc[nb][0];
            p0[1] = acc[nb][1];
            float* p1 = stage + (r0 + 8) * STG_STRIDE + n;
            p1[0] = acc[nb][2];
            p1[1] = acc[nb][3];
        }
        __syncthreads();

        // ========= coalesced store with bias ================================
#pragma unroll 2
        for (int rr = 0; rr < 8; rr++) {
            const int r = wid * 8 + rr;
            const int e = m0 + r;
            if (e < E) {
                const float* sp = stage + r * STG_STRIDE + 4 * lid;
                float4 v;
                v.x = sp[0] + bia0;
                v.y = sp[1] + bia1;
                v.z = sp[2] + bia2;
                v.w = sp[3] + bia3;
                *reinterpret_cast<float4*>(out + (size_t)e * 128 + 4 * lid) = v;
            }
        }
        __syncthreads();   // stage free before next tile's src_buf writes
    }
}

// ============================================================================
// Launch
// ============================================================================
extern "C" void kernel_launch(void* const* d_in, const int* in_sizes, int n_in,
                              void* d_out, int out_size) {
    const float* src   = (const float*)d_in[0];   // src_feat   [E,128] f32
    const float* dstf  = (const float*)d_in[1];   // dst_feat   [E,128] f32
    // d_in[2] = dst_ids (unused: seg_start = dst_max_eid - deg + 1)
    const int*   dme   = (const int*)  d_in[3];   // dst_max_eid [E] i32 or i64
    const float* deg   = (const float*)d_in[4];   // dst_deg    [E] f32
    const float* Wself = (const float*)d_in[5];   // [128,128] f32
    const float* bself = (const float*)d_in[6];   // [128] f32
    const float* Wnei  = (const float*)d_in[7];   // [128,128] f32
    const float* bnei  = (const float*)d_in[8];   // [128] f32
    float* out = (float*)d_out;

    const int E = in_sizes[4];
    const int num_tiles = (E + TILE_M - 1) / TILE_M;

    prep_w_kernel<<<32, 256>>>(Wself, Wnei, (const unsigned*)dme, E);

    int sm_count = 148;
    cudaDeviceGetAttribute(&sm_count, cudaDevAttrMultiProcessorCount, 0);
    int grid = OCC * sm_count;
    if (grid > num_tiles) grid = num_tiles;

    cudaFuncSetAttribute(fused_tsage_kernel,
                         cudaFuncAttributeMaxDynamicSharedMemorySize, SMEM_TOTAL);
    fused_tsage_kernel<<<grid, NTHREADS, SMEM_TOTAL>>>(
        src, dstf, dme, deg, bself, bnei, out, E, num_tiles);
}

// round 8
// speedup vs baseline: 1.5459x; 1.5459x over previous
#include <cuda_runtime.h>
#include <cuda_fp16.h>
#include <cstdint>

// ============================================================================
// FastTSAGEConv fused kernel for GB300 (plain sm_103 PTX feature set):
// legacy HMMA mma.sync.m16n8k16 fp16 (fp32 accum), 1-pass.
//
//   ss = seg_start (PROVEN: dst_deg = dst_max_eid - seg_start + 1)
//   hn[e]  = (sum_{j=ss..me} src_feat[j]) / (deg[e]+1)
//   out[e] = [dst_feat[e] | hn[e]] @ [W_self; W_neigh] + (b_self + b_neigh)
//
// R7 -> R8: revert the smem-stage experiment (straggler-amplified fallback).
// New producer: per warp, ONE monotone walk over rows [min ss, max me] of its
// 8 consecutive edges, resetting the accumulator at segment starts and
// snapshotting into the A tile when j hits an edge's me. Halves segsum row
// loads, removes the per-edge MLP cap, no fallback path, bounded stragglers.
// ============================================================================

#define TILE_M     64
#define NTHREADS   256
#define OCC        3

// ---- smem layout: A tile + aliased out-stage ----
static constexpr int A_STRIDE_B = 528;          // bytes per A row (256 fp16 + 8 pad)
static constexpr int STG_STRIDE = 136;          // floats per out-stage row (pad 8)
// A fp16 [64][528B] = 33792 B ; out stage fp32 [64][136] = 34816 B (aliased)
static constexpr int SMEM_TOTAL = TILE_M * STG_STRIDE * 4;   // 34816

// Pre-packed B fragments: [kstep 0..15][nblock 0..15][lane 0..31] x 2 u32
// (64 KB, stays hot in L1 across the whole kernel)
__device__ uint2 g_bfrag[16 * 16 * 32];
// dtype flag for dst_max_eid: 1 if int64, 0 if int32
__device__ int g_eid_is64;

// ============================ helpers ===================================
__device__ __forceinline__ uint32_t smem_to_u32(const void* smem_ptr) {
    uint32_t addr;
    asm("{ .reg .u64 tmp; cvta.to.shared.u64 tmp, %1; cvt.u32.u64 %0, tmp; }"
        : "=r"(addr) : "l"(smem_ptr));
    return addr;
}

__device__ __forceinline__ uint32_t f22u(float a, float b) {
    __half2 h = __floats2half2_rn(a, b);
    return *reinterpret_cast<uint32_t*>(&h);
}

__device__ __forceinline__ void mma16816(float* c, const uint32_t* a,
                                         uint32_t b0, uint32_t b1) {
    asm volatile(
        "mma.sync.aligned.m16n8k16.row.col.f32.f16.f16.f32 "
        "{%0,%1,%2,%3}, {%4,%5,%6,%7}, {%8,%9}, {%0,%1,%2,%3};\n"
        : "+f"(c[0]), "+f"(c[1]), "+f"(c[2]), "+f"(c[3])
        : "r"(a[0]), "r"(a[1]), "r"(a[2]), "r"(a[3]), "r"(b0), "r"(b1));
}

// ============================================================================
// Prep kernel (also hosts the dtype probe in block 0): pack
// B = [W_self; W_neigh] (256 x 128 f32) into fp16 MMA fragment layout.
// For kstep s (k0=16s), nblock nb (n0=8nb), lane l:
//   kA = 16s + (l%4)*2,  n = 8nb + l/4
//   reg0 = half2( B[kA][n],   B[kA+1][n] )
//   reg1 = half2( B[kA+8][n], B[kA+9][n] )
// Probe: view dst_max_eid as int64 at elements [E/4, E/4+256) (word indices
// < E under either dtype). True int64 (values in [0,E)) => all high words 0;
// int32 data there holds values ~E/2 != 0.
// ============================================================================
__global__ void prep_w_kernel(const float* __restrict__ Wself,
                              const float* __restrict__ Wneigh,
                              const unsigned* __restrict__ dme_words, int E) {
    if (blockIdx.x == 0) {
        __shared__ int nz;
        if (threadIdx.x == 0) nz = 0;
        __syncthreads();
        int i = E / 4 + threadIdx.x;
        unsigned hi = dme_words[2 * i + 1];
        if (hi != 0u) atomicAdd(&nz, 1);
        __syncthreads();
        if (threadIdx.x == 0) g_eid_is64 = (nz == 0) ? 1 : 0;
    }
    int idx = blockIdx.x * blockDim.x + threadIdx.x;    // 0..8191
    if (idx >= 16 * 16 * 32) return;
    int lane = idx & 31;
    int nb   = (idx >> 5) & 15;
    int s    = idx >> 9;
    int k0 = s * 16 + (lane & 3) * 2;
    int n  = nb * 8 + (lane >> 2);

    auto wc = [&](int k) -> float {
        return (k < 128) ? Wself[k * 128 + n] : Wneigh[(k - 128) * 128 + n];
    };
    uint2 v;
    v.x = f22u(wc(k0),     wc(k0 + 1));
    v.y = f22u(wc(k0 + 8), wc(k0 + 9));
    g_bfrag[idx] = v;
}

// ============================================================================
// Main persistent kernel — 3 CTAs/SM
// ============================================================================
__global__ void __launch_bounds__(NTHREADS, OCC)
fused_tsage_kernel(const float* __restrict__ src_feat,
                   const float* __restrict__ dst_feat,
                   const int*   __restrict__ dst_max_eid,
                   const float* __restrict__ dst_deg,
                   const float* __restrict__ b_self,
                   const float* __restrict__ b_neigh,
                   float* __restrict__ out,
                   int E, int num_tiles) {
    extern __shared__ char smem[];
    const uint32_t smem_base = smem_to_u32(smem);
    const int tid = threadIdx.x;
    const int wid = tid >> 5;
    const int lid = tid & 31;
    const int wm  = wid & 3;        // M-warp 0..3  (rows wm*16 .. +15)
    const int wn  = wid >> 2;       // N-warp 0..1  (cols wn*64 .. +63)
    const int is64 = g_eid_is64;
    const long long* dme64 = reinterpret_cast<const long long*>(dst_max_eid);

    // per-lane bias for the coalesced epilogue (cols 4*lid..4*lid+3)
    const float bia0 = b_self[4 * lid + 0] + b_neigh[4 * lid + 0];
    const float bia1 = b_self[4 * lid + 1] + b_neigh[4 * lid + 1];
    const float bia2 = b_self[4 * lid + 2] + b_neigh[4 * lid + 2];
    const float bia3 = b_self[4 * lid + 3] + b_neigh[4 * lid + 3];

    // ldmatrix per-lane address pieces (A tile, 528B row stride)
    const int ldsm_row = (lid & 7) + ((lid >> 3) & 1) * 8;   // row within 16
    const int ldsm_k16 = (lid >> 4) * 16;                    // +16B for k 8..15
    const uint32_t a_base = smem_base;

    float* stage = reinterpret_cast<float*>(smem);           // fp32 view (aliased)
    // per-warp B fragment pointer (this warp's wn half), L1-resident
    const uint2* __restrict__ bfrag_w = g_bfrag + (size_t)(wn * 8) * 32 + lid;

    for (int t = blockIdx.x; t < num_tiles; t += gridDim.x) {
        const int m0 = t * TILE_M;

        // ========= phase 1: dst_feat -> A cols 0..127 (independent loads) ===
#pragma unroll 4
        for (int rr = 0; rr < 8; rr++) {
            const int r = wid * 8 + rr;
            const int e = m0 + r;
            if (e < E) {
                float4 dv = __ldg(reinterpret_cast<const float4*>(
                    dst_feat + (size_t)e * 128 + 4 * lid));
                uint32_t addr = a_base + (uint32_t)r * A_STRIDE_B + 8u * lid;
                uint32_t d01 = f22u(dv.x, dv.y);
                uint32_t d23 = f22u(dv.z, dv.w);
                asm volatile("st.shared.v2.b32 [%0], {%1,%2};"
                             :: "r"(addr), "r"(d01), "r"(d23) : "memory");
            }
        }

        // ========= phase 2: grouped segment walk -> A cols 128..255 =========
        // Per-warp: 8 consecutive edges share 1-2 segments (ss = seg_start,
        // non-decreasing). Walk rows [ssA[0], max me] once; reset accumulator
        // at segment starts; snapshot acc*inv into A when j == meA[q].
        {
            int   ssA[8], meA[8];
            float invA[8];
#pragma unroll
            for (int q = 0; q < 8; q++) {
                const int e = m0 + wid * 8 + q;
                int me; float dg;
                if (e < E) {
                    me = is64 ? (int)dme64[e] : dst_max_eid[e];
                    dg = dst_deg[e];
                    if (me >= E) me = E - 1;       // bounded under any mis-parse
                    if (me < 0)  me = 0;
                } else { me = -1; dg = 0.f; }
                int ss = me - (int)dg + 1;
                if (ss < 0) ss = 0;
                ssA[q] = ss; meA[q] = me;
                invA[q] = 1.0f / (dg + 1.0f);
            }
            int jmax = meA[0];
#pragma unroll
            for (int q = 1; q < 8; q++) jmax = max(jmax, meA[q]);
            const int j0 = ssA[0];

            float ax = 0.f, ay = 0.f, az = 0.f, aw = 0.f;
            int cur_ss = j0;
#pragma unroll 2
            for (int j = j0; j <= jmax; j++) {
                // segment boundary reset (before adding row j)
                bool rst = false;
#pragma unroll
                for (int q = 1; q < 8; q++) rst |= (ssA[q] == j);
                if (rst && j != cur_ss) { ax = ay = az = aw = 0.f; cur_ss = j; }

                float4 v = __ldg(reinterpret_cast<const float4*>(
                    src_feat + (size_t)j * 128 + 4 * lid));
                ax += v.x; ay += v.y; az += v.z; aw += v.w;

                // snapshots (after adding row j)
#pragma unroll
                for (int q = 0; q < 8; q++) {
                    if (meA[q] == j) {
                        const float inv = invA[q];
                        uint32_t addr = a_base + (uint32_t)(wid * 8 + q) * A_STRIDE_B
                                      + 256u + 8u * lid;
                        uint32_t h01 = f22u(ax * inv, ay * inv);
                        uint32_t h23 = f22u(az * inv, aw * inv);
                        asm volatile("st.shared.v2.b32 [%0], {%1,%2};"
                                     :: "r"(addr), "r"(h01), "r"(h23) : "memory");
                    }
                }
            }
        }
        __syncthreads();

        // ========= MMA phase: warp tile 16x64, K=256 ========================
        float acc[8][4];
#pragma unroll
        for (int nb = 0; nb < 8; nb++)
#pragma unroll
            for (int q = 0; q < 4; q++) acc[nb][q] = 0.f;

#pragma unroll 4
        for (int s = 0; s < 16; s++) {
            uint32_t a[4];
            {
                const int row0 = wm * 16;
                uint32_t addr = a_base + (uint32_t)(row0 + ldsm_row) * A_STRIDE_B
                              + (uint32_t)ldsm_k16 + (uint32_t)s * 32u;
                asm volatile(
                    "ldmatrix.sync.aligned.m8n8.x4.shared.b16 {%0,%1,%2,%3}, [%4];"
                    : "=r"(a[0]), "=r"(a[1]), "=r"(a[2]), "=r"(a[3])
                    : "r"(addr));
            }
            const uint2* bp = bfrag_w + (size_t)(s * 16) * 32;
#pragma unroll
            for (int nb = 0; nb < 8; nb++) {
                uint2 b = __ldg(bp + (size_t)nb * 32);
                mma16816(acc[nb], a, b.x, b.y);
            }
        }
        __syncthreads();   // all warps done reading A before stage overwrite

        // ========= epilogue: regs -> fp32 stage (aliases A) =================
#pragma unroll
        for (int nb = 0; nb < 8; nb++) {
            const int r0 = wm * 16 + (lid >> 2);
            const int n  = wn * 64 + nb * 8 + (lid & 3) * 2;
            float* p0 = stage + r0 * STG_STRIDE + n;
            p0[0] = acc[nb][0];
            p0[1] = acc[nb][1];
            float* p1 = stage + (r0 + 8) * STG_STRIDE + n;
            p1[0] = acc[nb][2];
            p1[1] = acc[nb][3];
        }
        __syncthreads();

        // ========= coalesced store with bias ================================
#pragma unroll 2
        for (int rr = 0; rr < 8; rr++) {
            const int r = wid * 8 + rr;
            const int e = m0 + r;
            if (e < E) {
                const float* sp = stage + r * STG_STRIDE + 4 * lid;
                float4 v;
                v.x = sp[0] + bia0;
                v.y = sp[1] + bia1;
                v.z = sp[2] + bia2;
                v.w = sp[3] + bia3;
                *reinterpret_cast<float4*>(out + (size_t)e * 128 + 4 * lid) = v;
            }
        }
        __syncthreads();   // stage free before next tile's A writes
    }
}

// ============================================================================
// Launch
// ============================================================================
extern "C" void kernel_launch(void* const* d_in, const int* in_sizes, int n_in,
                              void* d_out, int out_size) {
    const float* src   = (const float*)d_in[0];   // src_feat   [E,128] f32
    const float* dstf  = (const float*)d_in[1];   // dst_feat   [E,128] f32
    // d_in[2] = dst_ids (unused: seg_start = dst_max_eid - deg + 1)
    const int*   dme   = (const int*)  d_in[3];   // dst_max_eid [E] i32 or i64
    const float* deg   = (const float*)d_in[4];   // dst_deg    [E] f32
    const float* Wself = (const float*)d_in[5];   // [128,128] f32
    const float* bself = (const float*)d_in[6];   // [128] f32
    const float* Wnei  = (const float*)d_in[7];   // [128,128] f32
    const float* bnei  = (const float*)d_in[8];   // [128] f32
    float* out = (float*)d_out;

    const int E = in_sizes[4];
    const int num_tiles = (E + TILE_M - 1) / TILE_M;

    prep_w_kernel<<<32, 256>>>(Wself, Wnei, (const unsigned*)dme, E);

    int sm_count = 148;
    cudaDeviceGetAttribute(&sm_count, cudaDevAttrMultiProcessorCount, 0);
    int grid = OCC * sm_count;
    if (grid > num_tiles) grid = num_tiles;

    cudaFuncSetAttribute(fused_tsage_kernel,
                         cudaFuncAttributeMaxDynamicSharedMemorySize, SMEM_TOTAL);
    fused_tsage_kernel<<<grid, NTHREADS, SMEM_TOTAL>>>(
        src, dstf, dme, deg, bself, bnei, out, E, num_tiles);
}

// round 9
// speedup vs baseline: 1.6027x; 1.0367x over previous
#include <cuda_runtime.h>
#include <cuda_fp16.h>
#include <cstdint>

// ============================================================================
// FastTSAGEConv fused kernel for GB300 (plain sm_103 PTX feature set):
// legacy HMMA mma.sync.m16n8k16 fp16 (fp32 accum), 1-pass.
//
//   ss = seg_start (PROVEN: dst_deg = dst_max_eid - seg_start + 1)
//   hn[e]  = (sum_{j=ss..me} src_feat[j]) / (deg[e]+1)
//   out[e] = [dst_feat[e] | hn[e]] @ [W_self; W_neigh] + (b_self + b_neigh)
//
// R8 -> R9: the grouped walk was algorithmically right but ran at MLP 1
// (load->add->load chain). Now: 4-deep software-prefetch ring over the walk
// (addresses independent of accumulation) -> 4 loads in flight; and split
// each warp's 8 edges into two 4-edge walks to fit OCC-3 registers.
// ============================================================================

#define TILE_M     64
#define NTHREADS   256
#define OCC        3

// ---- smem layout: A tile + aliased out-stage ----
static constexpr int A_STRIDE_B = 528;          // bytes per A row (256 fp16 + 8 pad)
static constexpr int STG_STRIDE = 136;          // floats per out-stage row (pad 8)
// A fp16 [64][528B] = 33792 B ; out stage fp32 [64][136] = 34816 B (aliased)
static constexpr int SMEM_TOTAL = TILE_M * STG_STRIDE * 4;   // 34816

// Pre-packed B fragments: [kstep 0..15][nblock 0..15][lane 0..31] x 2 u32
// (64 KB, stays hot in L1 across the whole kernel)
__device__ uint2 g_bfrag[16 * 16 * 32];
// dtype flag for dst_max_eid: 1 if int64, 0 if int32
__device__ int g_eid_is64;

// ============================ helpers ===================================
__device__ __forceinline__ uint32_t smem_to_u32(const void* smem_ptr) {
    uint32_t addr;
    asm("{ .reg .u64 tmp; cvta.to.shared.u64 tmp, %1; cvt.u32.u64 %0, tmp; }"
        : "=r"(addr) : "l"(smem_ptr));
    return addr;
}

__device__ __forceinline__ uint32_t f22u(float a, float b) {
    __half2 h = __floats2half2_rn(a, b);
    return *reinterpret_cast<uint32_t*>(&h);
}

__device__ __forceinline__ void mma16816(float* c, const uint32_t* a,
                                         uint32_t b0, uint32_t b1) {
    asm volatile(
        "mma.sync.aligned.m16n8k16.row.col.f32.f16.f16.f32 "
        "{%0,%1,%2,%3}, {%4,%5,%6,%7}, {%8,%9}, {%0,%1,%2,%3};\n"
        : "+f"(c[0]), "+f"(c[1]), "+f"(c[2]), "+f"(c[3])
        : "r"(a[0]), "r"(a[1]), "r"(a[2]), "r"(a[3]), "r"(b0), "r"(b1));
}

// ============================================================================
// Prep kernel (also hosts the dtype probe in block 0): pack
// B = [W_self; W_neigh] (256 x 128 f32) into fp16 MMA fragment layout.
// For kstep s (k0=16s), nblock nb (n0=8nb), lane l:
//   kA = 16s + (l%4)*2,  n = 8nb + l/4
//   reg0 = half2( B[kA][n],   B[kA+1][n] )
//   reg1 = half2( B[kA+8][n], B[kA+9][n] )
// Probe: view dst_max_eid as int64 at elements [E/4, E/4+256) (word indices
// < E under either dtype). True int64 (values in [0,E)) => all high words 0;
// int32 data there holds values ~E/2 != 0.
// ============================================================================
__global__ void prep_w_kernel(const float* __restrict__ Wself,
                              const float* __restrict__ Wneigh,
                              const unsigned* __restrict__ dme_words, int E) {
    if (blockIdx.x == 0) {
        __shared__ int nz;
        if (threadIdx.x == 0) nz = 0;
        __syncthreads();
        int i = E / 4 + threadIdx.x;
        unsigned hi = dme_words[2 * i + 1];
        if (hi != 0u) atomicAdd(&nz, 1);
        __syncthreads();
        if (threadIdx.x == 0) g_eid_is64 = (nz == 0) ? 1 : 0;
    }
    int idx = blockIdx.x * blockDim.x + threadIdx.x;    // 0..8191
    if (idx >= 16 * 16 * 32) return;
    int lane = idx & 31;
    int nb   = (idx >> 5) & 15;
    int s    = idx >> 9;
    int k0 = s * 16 + (lane & 3) * 2;
    int n  = nb * 8 + (lane >> 2);

    auto wc = [&](int k) -> float {
        return (k < 128) ? Wself[k * 128 + n] : Wneigh[(k - 128) * 128 + n];
    };
    uint2 v;
    v.x = f22u(wc(k0),     wc(k0 + 1));
    v.y = f22u(wc(k0 + 8), wc(k0 + 9));
    g_bfrag[idx] = v;
}

// ============================================================================
// Main persistent kernel — 3 CTAs/SM
// ============================================================================
__global__ void __launch_bounds__(NTHREADS, OCC)
fused_tsage_kernel(const float* __restrict__ src_feat,
                   const float* __restrict__ dst_feat,
                   const int*   __restrict__ dst_max_eid,
                   const float* __restrict__ dst_deg,
                   const float* __restrict__ b_self,
                   const float* __restrict__ b_neigh,
                   float* __restrict__ out,
                   int E, int num_tiles) {
    extern __shared__ char smem[];
    const uint32_t smem_base = smem_to_u32(smem);
    const int tid = threadIdx.x;
    const int wid = tid >> 5;
    const int lid = tid & 31;
    const int wm  = wid & 3;        // M-warp 0..3  (rows wm*16 .. +15)
    const int wn  = wid >> 2;       // N-warp 0..1  (cols wn*64 .. +63)
    const int is64 = g_eid_is64;
    const long long* dme64 = reinterpret_cast<const long long*>(dst_max_eid);

    // per-lane bias for the coalesced epilogue (cols 4*lid..4*lid+3)
    const float bia0 = b_self[4 * lid + 0] + b_neigh[4 * lid + 0];
    const float bia1 = b_self[4 * lid + 1] + b_neigh[4 * lid + 1];
    const float bia2 = b_self[4 * lid + 2] + b_neigh[4 * lid + 2];
    const float bia3 = b_self[4 * lid + 3] + b_neigh[4 * lid + 3];

    // ldmatrix per-lane address pieces (A tile, 528B row stride)
    const int ldsm_row = (lid & 7) + ((lid >> 3) & 1) * 8;   // row within 16
    const int ldsm_k16 = (lid >> 4) * 16;                    // +16B for k 8..15
    const uint32_t a_base = smem_base;

    float* stage = reinterpret_cast<float*>(smem);           // fp32 view (aliased)
    // per-warp B fragment pointer (this warp's wn half), L1-resident
    const uint2* __restrict__ bfrag_w = g_bfrag + (size_t)(wn * 8) * 32 + lid;

    for (int t = blockIdx.x; t < num_tiles; t += gridDim.x) {
        const int m0 = t * TILE_M;

        // ========= phase 1: dst_feat -> A cols 0..127 (independent loads) ===
#pragma unroll 4
        for (int rr = 0; rr < 8; rr++) {
            const int r = wid * 8 + rr;
            const int e = m0 + r;
            if (e < E) {
                float4 dv = __ldg(reinterpret_cast<const float4*>(
                    dst_feat + (size_t)e * 128 + 4 * lid));
                uint32_t addr = a_base + (uint32_t)r * A_STRIDE_B + 8u * lid;
                uint32_t d01 = f22u(dv.x, dv.y);
                uint32_t d23 = f22u(dv.z, dv.w);
                asm volatile("st.shared.v2.b32 [%0], {%1,%2};"
                             :: "r"(addr), "r"(d01), "r"(d23) : "memory");
            }
        }

        // ========= phase 2: two 4-edge prefetched walks -> A cols 128..255 ==
        // ss = seg_start (non-decreasing); walk rows [ssA[0], max me] once,
        // reset accumulator at segment starts, snapshot when j == meA[q].
        // 4-deep prefetch ring keeps 4 row loads in flight (MLP 4).
#pragma unroll 1
        for (int h = 0; h < 2; h++) {
            int   ssA[4], meA[4];
            float invA[4];
#pragma unroll
            for (int q = 0; q < 4; q++) {
                const int e = m0 + wid * 8 + h * 4 + q;
                int me; float dg;
                if (e < E) {
                    me = is64 ? (int)dme64[e] : dst_max_eid[e];
                    dg = dst_deg[e];
                    if (me >= E) me = E - 1;       // bounded under any mis-parse
                    if (me < 0)  me = 0;
                } else { me = -1; dg = 0.f; }
                int ss = me - (int)dg + 1;
                if (ss < 0) ss = 0;
                ssA[q] = ss; meA[q] = me;
                invA[q] = 1.0f / (dg + 1.0f);
            }
            int jmax = meA[0];
#pragma unroll
            for (int q = 1; q < 4; q++) jmax = max(jmax, meA[q]);
            const int j0 = ssA[0];

            const float* bp = src_feat + (size_t)j0 * 128 + 4 * lid;
            float4 z4 = make_float4(0.f, 0.f, 0.f, 0.f);
            float4 buf0 = (j0 + 0 <= jmax) ? __ldg((const float4*)(bp))       : z4;
            float4 buf1 = (j0 + 1 <= jmax) ? __ldg((const float4*)(bp + 128)) : z4;
            float4 buf2 = (j0 + 2 <= jmax) ? __ldg((const float4*)(bp + 256)) : z4;
            float4 buf3 = (j0 + 3 <= jmax) ? __ldg((const float4*)(bp + 384)) : z4;

            float ax = 0.f, ay = 0.f, az = 0.f, aw = 0.f;
#pragma unroll 1
            for (int j = j0; j <= jmax; j += 4) {
#pragma unroll
                for (int i = 0; i < 4; i++) {
                    const int jj = j + i;
                    if (jj <= jmax) {
                        float4 v = (i == 0) ? buf0 : (i == 1) ? buf1
                                 : (i == 2) ? buf2 : buf3;
                        // prefetch jj+4 into the slot just consumed
                        const int jn = jj + 4;
                        float4 nv = z4;
                        if (jn <= jmax)
                            nv = __ldg((const float4*)(
                                src_feat + (size_t)jn * 128 + 4 * lid));
                        if (i == 0) buf0 = nv; else if (i == 1) buf1 = nv;
                        else if (i == 2) buf2 = nv; else buf3 = nv;

                        // segment-boundary reset (before adding row jj)
                        bool rst = (ssA[1] == jj) | (ssA[2] == jj) | (ssA[3] == jj);
                        if (rst) { ax = 0.f; ay = 0.f; az = 0.f; aw = 0.f; }
                        ax += v.x; ay += v.y; az += v.z; aw += v.w;

                        // snapshots (after adding row jj)
#pragma unroll
                        for (int q = 0; q < 4; q++) {
                            if (meA[q] == jj) {
                                const float inv = invA[q];
                                uint32_t addr = a_base
                                    + (uint32_t)(wid * 8 + h * 4 + q) * A_STRIDE_B
                                    + 256u + 8u * lid;
                                uint32_t h01 = f22u(ax * inv, ay * inv);
                                uint32_t h23 = f22u(az * inv, aw * inv);
                                asm volatile("st.shared.v2.b32 [%0], {%1,%2};"
                                             :: "r"(addr), "r"(h01), "r"(h23)
                                             : "memory");
                            }
                        }
                    }
                }
            }
        }
        __syncthreads();

        // ========= MMA phase: warp tile 16x64, K=256 ========================
        float acc[8][4];
#pragma unroll
        for (int nb = 0; nb < 8; nb++)
#pragma unroll
            for (int q = 0; q < 4; q++) acc[nb][q] = 0.f;

#pragma unroll 4
        for (int s = 0; s < 16; s++) {
            uint32_t a[4];
            {
                const int row0 = wm * 16;
                uint32_t addr = a_base + (uint32_t)(row0 + ldsm_row) * A_STRIDE_B
                              + (uint32_t)ldsm_k16 + (uint32_t)s * 32u;
                asm volatile(
                    "ldmatrix.sync.aligned.m8n8.x4.shared.b16 {%0,%1,%2,%3}, [%4];"
                    : "=r"(a[0]), "=r"(a[1]), "=r"(a[2]), "=r"(a[3])
                    : "r"(addr));
            }
            const uint2* bp = bfrag_w + (size_t)(s * 16) * 32;
#pragma unroll
            for (int nb = 0; nb < 8; nb++) {
                uint2 b = __ldg(bp + (size_t)nb * 32);
                mma16816(acc[nb], a, b.x, b.y);
            }
        }
        __syncthreads();   // all warps done reading A before stage overwrite

        // ========= epilogue: regs -> fp32 stage (aliases A) =================
#pragma unroll
        for (int nb = 0; nb < 8; nb++) {
            const int r0 = wm * 16 + (lid >> 2);
            const int n  = wn * 64 + nb * 8 + (lid & 3) * 2;
            float* p0 = stage + r0 * STG_STRIDE + n;
            p0[0] = acc[nb][0];
            p0[1] = acc[nb][1];
            float* p1 = stage + (r0 + 8) * STG_STRIDE + n;
            p1[0] = acc[nb][2];
            p1[1] = acc[nb][3];
        }
        __syncthreads();

        // ========= coalesced store with bias ================================
#pragma unroll 2
        for (int rr = 0; rr < 8; rr++) {
            const int r = wid * 8 + rr;
            const int e = m0 + r;
            if (e < E) {
                const float* sp = stage + r * STG_STRIDE + 4 * lid;
                float4 v;
                v.x = sp[0] + bia0;
                v.y = sp[1] + bia1;
                v.z = sp[2] + bia2;
                v.w = sp[3] + bia3;
                *reinterpret_cast<float4*>(out + (size_t)e * 128 + 4 * lid) = v;
            }
        }
        __syncthreads();   // stage free before next tile's A writes
    }
}

// ============================================================================
// Launch
// ============================================================================
extern "C" void kernel_launch(void* const* d_in, const int* in_sizes, int n_in,
                              void* d_out, int out_size) {
    const float* src   = (const float*)d_in[0];   // src_feat   [E,128] f32
    const float* dstf  = (const float*)d_in[1];   // dst_feat   [E,128] f32
    // d_in[2] = dst_ids (unused: seg_start = dst_max_eid - deg + 1)
    const int*   dme   = (const int*)  d_in[3];   // dst_max_eid [E] i32 or i64
    const float* deg   = (const float*)d_in[4];   // dst_deg    [E] f32
    const float* Wself = (const float*)d_in[5];   // [128,128] f32
    const float* bself = (const float*)d_in[6];   // [128] f32
    const float* Wnei  = (const float*)d_in[7];   // [128,128] f32
    const float* bnei  = (const float*)d_in[8];   // [128] f32
    float* out = (float*)d_out;

    const int E = in_sizes[4];
    const int num_tiles = (E + TILE_M - 1) / TILE_M;

    prep_w_kernel<<<32, 256>>>(Wself, Wnei, (const unsigned*)dme, E);

    int sm_count = 148;
    cudaDeviceGetAttribute(&sm_count, cudaDevAttrMultiProcessorCount, 0);
    int grid = OCC * sm_count;
    if (grid > num_tiles) grid = num_tiles;

    cudaFuncSetAttribute(fused_tsage_kernel,
                         cudaFuncAttributeMaxDynamicSharedMemorySize, SMEM_TOTAL);
    fused_tsage_kernel<<<grid, NTHREADS, SMEM_TOTAL>>>(
        src, dstf, dme, deg, bself, bnei, out, E, num_tiles);
}

// round 10
// speedup vs baseline: 1.8160x; 1.1331x over previous
#include <cuda_runtime.h>
#include <cuda_fp16.h>
#include <cstdint>

// ============================================================================
// FastTSAGEConv fused kernel for GB300 (plain sm_103 PTX feature set):
// legacy HMMA mma.sync.m16n8k16 fp16 (fp32 accum), 1-pass.
//
//   ss = seg_start (dst_deg = dst_max_eid - seg_start + 1)
//   hn[e]  = (sum_{j=ss..me} src_feat[j]) / (deg[e]+1)
//   out[e] = [dst_feat[e] | hn[e]] @ [W_self; W_neigh] + (b_self + b_neigh)
//
// R9 -> R10: abandon the shared-prefix walk (2 failed rounds: per-row control
// logic + in-order issue killed it). Back to the R6 per-edge frame; producer
// MLP fixed for in-order issue: each thread interleaves TWO edges' segsum
// chains, 2 rows each per iteration -> 4 independent predicated loads issued
// back-to-back before any dependent FADD -> one L2 stall covers 4 rows.
// OCC 3 (84-reg cap, no spills) since per-warp ILP replaces the 4th CTA.
// ============================================================================

#define TILE_M     64
#define NTHREADS   256
#define OCC        3

// ---- smem layout: A tile + aliased out-stage ----
static constexpr int A_STRIDE_B = 528;          // bytes per A row (256 fp16 + 8 pad)
static constexpr int STG_STRIDE = 136;          // floats per out-stage row (pad 8)
// A fp16 [64][528B] = 33792 B ; out stage fp32 [64][136] = 34816 B (aliased)
static constexpr int SMEM_TOTAL = TILE_M * STG_STRIDE * 4;   // 34816

// Pre-packed B fragments: [kstep 0..15][nblock 0..15][lane 0..31] x 2 u32
// (64 KB, stays hot in L1 across the whole kernel)
__device__ uint2 g_bfrag[16 * 16 * 32];
// dtype flag for dst_max_eid: 1 if int64, 0 if int32
__device__ int g_eid_is64;

// ============================ helpers ===================================
__device__ __forceinline__ uint32_t smem_to_u32(const void* smem_ptr) {
    uint32_t addr;
    asm("{ .reg .u64 tmp; cvta.to.shared.u64 tmp, %1; cvt.u32.u64 %0, tmp; }"
        : "=r"(addr) : "l"(smem_ptr));
    return addr;
}

__device__ __forceinline__ uint32_t f22u(float a, float b) {
    __half2 h = __floats2half2_rn(a, b);
    return *reinterpret_cast<uint32_t*>(&h);
}

__device__ __forceinline__ void mma16816(float* c, const uint32_t* a,
                                         uint32_t b0, uint32_t b1) {
    asm volatile(
        "mma.sync.aligned.m16n8k16.row.col.f32.f16.f16.f32 "
        "{%0,%1,%2,%3}, {%4,%5,%6,%7}, {%8,%9}, {%0,%1,%2,%3};\n"
        : "+f"(c[0]), "+f"(c[1]), "+f"(c[2]), "+f"(c[3])
        : "r"(a[0]), "r"(a[1]), "r"(a[2]), "r"(a[3]), "r"(b0), "r"(b1));
}

// ============================================================================
// Prep kernel (also hosts the dtype probe in block 0): pack
// B = [W_self; W_neigh] (256 x 128 f32) into fp16 MMA fragment layout.
// For kstep s (k0=16s), nblock nb (n0=8nb), lane l:
//   kA = 16s + (l%4)*2,  n = 8nb + l/4
//   reg0 = half2( B[kA][n],   B[kA+1][n] )
//   reg1 = half2( B[kA+8][n], B[kA+9][n] )
// Probe: view dst_max_eid as int64 at elements [E/4, E/4+256) (word indices
// < E under either dtype). True int64 (values in [0,E)) => all high words 0;
// int32 data there holds values ~E/2 != 0.
// ============================================================================
__global__ void prep_w_kernel(const float* __restrict__ Wself,
                              const float* __restrict__ Wneigh,
                              const unsigned* __restrict__ dme_words, int E) {
    if (blockIdx.x == 0) {
        __shared__ int nz;
        if (threadIdx.x == 0) nz = 0;
        __syncthreads();
        int i = E / 4 + threadIdx.x;
        unsigned hi = dme_words[2 * i + 1];
        if (hi != 0u) atomicAdd(&nz, 1);
        __syncthreads();
        if (threadIdx.x == 0) g_eid_is64 = (nz == 0) ? 1 : 0;
    }
    int idx = blockIdx.x * blockDim.x + threadIdx.x;    // 0..8191
    if (idx >= 16 * 16 * 32) return;
    int lane = idx & 31;
    int nb   = (idx >> 5) & 15;
    int s    = idx >> 9;
    int k0 = s * 16 + (lane & 3) * 2;
    int n  = nb * 8 + (lane >> 2);

    auto wc = [&](int k) -> float {
        return (k < 128) ? Wself[k * 128 + n] : Wneigh[(k - 128) * 128 + n];
    };
    uint2 v;
    v.x = f22u(wc(k0),     wc(k0 + 1));
    v.y = f22u(wc(k0 + 8), wc(k0 + 9));
    g_bfrag[idx] = v;
}

// ============================================================================
// Main persistent kernel — 3 CTAs/SM
// ============================================================================
__global__ void __launch_bounds__(NTHREADS, OCC)
fused_tsage_kernel(const float* __restrict__ src_feat,
                   const float* __restrict__ dst_feat,
                   const int*   __restrict__ dst_max_eid,
                   const float* __restrict__ dst_deg,
                   const float* __restrict__ b_self,
                   const float* __restrict__ b_neigh,
                   float* __restrict__ out,
                   int E, int num_tiles) {
    extern __shared__ char smem[];
    const uint32_t smem_base = smem_to_u32(smem);
    const int tid = threadIdx.x;
    const int wid = tid >> 5;
    const int lid = tid & 31;
    const int wm  = wid & 3;        // M-warp 0..3  (rows wm*16 .. +15)
    const int wn  = wid >> 2;       // N-warp 0..1  (cols wn*64 .. +63)
    const int is64 = g_eid_is64;
    const long long* dme64 = reinterpret_cast<const long long*>(dst_max_eid);

    // per-lane bias for the coalesced epilogue (cols 4*lid..4*lid+3)
    const float bia0 = b_self[4 * lid + 0] + b_neigh[4 * lid + 0];
    const float bia1 = b_self[4 * lid + 1] + b_neigh[4 * lid + 1];
    const float bia2 = b_self[4 * lid + 2] + b_neigh[4 * lid + 2];
    const float bia3 = b_self[4 * lid + 3] + b_neigh[4 * lid + 3];

    // ldmatrix per-lane address pieces (A tile, 528B row stride)
    const int ldsm_row = (lid & 7) + ((lid >> 3) & 1) * 8;   // row within 16
    const int ldsm_k16 = (lid >> 4) * 16;                    // +16B for k 8..15
    const uint32_t a_base = smem_base;

    float* stage = reinterpret_cast<float*>(smem);           // fp32 view (aliased)
    // per-warp B fragment pointer (this warp's wn half), L1-resident
    const uint2* __restrict__ bfrag_w = g_bfrag + (size_t)(wn * 8) * 32 + lid;

    const float4 z4 = make_float4(0.f, 0.f, 0.f, 0.f);

    for (int t = blockIdx.x; t < num_tiles; t += gridDim.x) {
        const int m0 = t * TILE_M;

        // ========= producer: 4 pairs of edges, 2 chains interleaved =========
#pragma unroll 1
        for (int u = 0; u < 4; u++) {
            const int r0 = wid * 8 + 2 * u;          // tile row of edge 0
            const int e0 = m0 + r0;                  // edge 0 ; edge 1 = e0+1
            const bool g0 = (e0 < E), g1 = (e0 + 1 < E);

            // dst loads (2 independent, issued first)
            float4 dv0 = z4, dv1 = z4;
            if (g0) dv0 = __ldg(reinterpret_cast<const float4*>(
                dst_feat + (size_t)e0 * 128 + 4 * lid));
            if (g1) dv1 = __ldg(reinterpret_cast<const float4*>(
                dst_feat + (size_t)(e0 + 1) * 128 + 4 * lid));

            // segment metadata
            int me0 = 0, me1 = 0; float dg0 = 0.f, dg1 = 0.f;
            if (g0) { me0 = is64 ? (int)dme64[e0] : dst_max_eid[e0];
                      dg0 = dst_deg[e0]; }
            if (g1) { me1 = is64 ? (int)dme64[e0 + 1] : dst_max_eid[e0 + 1];
                      dg1 = dst_deg[e0 + 1]; }
            if (me0 >= E) me0 = E - 1;  if (me0 < 0) me0 = 0;
            if (me1 >= E) me1 = E - 1;  if (me1 < 0) me1 = 0;
            int ss0 = me0 - (int)dg0 + 1;  if (ss0 < 0) ss0 = 0;
            int ss1 = me1 - (int)dg1 + 1;  if (ss1 < 0) ss1 = 0;
            const int c0 = g0 ? (me0 - ss0 + 1) : 0;
            const int c1 = g1 ? (me1 - ss1 + 1) : 0;

            const float4* p0 = reinterpret_cast<const float4*>(
                src_feat + (size_t)ss0 * 128 + 4 * lid);
            const float4* p1 = reinterpret_cast<const float4*>(
                src_feat + (size_t)ss1 * 128 + 4 * lid);

            // interleaved dual-chain segsum: 4 independent loads per iter
            float a0x = 0.f, a0y = 0.f, a0z = 0.f, a0w = 0.f;
            float a1x = 0.f, a1y = 0.f, a1z = 0.f, a1w = 0.f;
            int i0 = 0, i1 = 0;
#pragma unroll 1
            while ((i0 < c0) | (i1 < c1)) {
                float4 x0 = (i0     < c0) ? __ldg(p0 + (size_t)(i0)     * 32) : z4;
                float4 x1 = (i1     < c1) ? __ldg(p1 + (size_t)(i1)     * 32) : z4;
                float4 x2 = (i0 + 1 < c0) ? __ldg(p0 + (size_t)(i0 + 1) * 32) : z4;
                float4 x3 = (i1 + 1 < c1) ? __ldg(p1 + (size_t)(i1 + 1) * 32) : z4;
                a0x += x0.x + x2.x; a0y += x0.y + x2.y;
                a0z += x0.z + x2.z; a0w += x0.w + x2.w;
                a1x += x1.x + x3.x; a1y += x1.y + x3.y;
                a1z += x1.z + x3.z; a1w += x1.w + x3.w;
                i0 += 2; i1 += 2;
            }

            // stores: dst halves + hn halves (fp16)
            if (g0) {
                const float inv0 = 1.0f / (dg0 + 1.0f);
                uint32_t addr = a_base + (uint32_t)r0 * A_STRIDE_B + 8u * lid;
                uint32_t d01 = f22u(dv0.x, dv0.y), d23 = f22u(dv0.z, dv0.w);
                asm volatile("st.shared.v2.b32 [%0], {%1,%2};"
                             :: "r"(addr), "r"(d01), "r"(d23) : "memory");
                uint32_t h01 = f22u(a0x * inv0, a0y * inv0);
                uint32_t h23 = f22u(a0z * inv0, a0w * inv0);
                asm volatile("st.shared.v2.b32 [%0], {%1,%2};"
                             :: "r"(addr + 256u), "r"(h01), "r"(h23) : "memory");
            }
            if (g1) {
                const float inv1 = 1.0f / (dg1 + 1.0f);
                uint32_t addr = a_base + (uint32_t)(r0 + 1) * A_STRIDE_B + 8u * lid;
                uint32_t d01 = f22u(dv1.x, dv1.y), d23 = f22u(dv1.z, dv1.w);
                asm volatile("st.shared.v2.b32 [%0], {%1,%2};"
                             :: "r"(addr), "r"(d01), "r"(d23) : "memory");
                uint32_t h01 = f22u(a1x * inv1, a1y * inv1);
                uint32_t h23 = f22u(a1z * inv1, a1w * inv1);
                asm volatile("st.shared.v2.b32 [%0], {%1,%2};"
                             :: "r"(addr + 256u), "r"(h01), "r"(h23) : "memory");
            }
        }
        __syncthreads();

        // ========= MMA phase: warp tile 16x64, K=256 ========================
        float acc[8][4];
#pragma unroll
        for (int nb = 0; nb < 8; nb++)
#pragma unroll
            for (int q = 0; q < 4; q++) acc[nb][q] = 0.f;

#pragma unroll 4
        for (int s = 0; s < 16; s++) {
            uint32_t a[4];
            {
                const int row0 = wm * 16;
                uint32_t addr = a_base + (uint32_t)(row0 + ldsm_row) * A_STRIDE_B
                              + (uint32_t)ldsm_k16 + (uint32_t)s * 32u;
                asm volatile(
                    "ldmatrix.sync.aligned.m8n8.x4.shared.b16 {%0,%1,%2,%3}, [%4];"
                    : "=r"(a[0]), "=r"(a[1]), "=r"(a[2]), "=r"(a[3])
                    : "r"(addr));
            }
            const uint2* bp = bfrag_w + (size_t)(s * 16) * 32;
#pragma unroll
            for (int nb = 0; nb < 8; nb++) {
                uint2 b = __ldg(bp + (size_t)nb * 32);
                mma16816(acc[nb], a, b.x, b.y);
            }
        }
        __syncthreads();   // all warps done reading A before stage overwrite

        // ========= epilogue: regs -> fp32 stage (aliases A) =================
#pragma unroll
        for (int nb = 0; nb < 8; nb++) {
            const int r0 = wm * 16 + (lid >> 2);
            const int n  = wn * 64 + nb * 8 + (lid & 3) * 2;
            float* p0 = stage + r0 * STG_STRIDE + n;
            p0[0] = acc[nb][0];
            p0[1] = acc[nb][1];
            float* p1 = stage + (r0 + 8) * STG_STRIDE + n;
            p1[0] = acc[nb][2];
            p1[1] = acc[nb][3];
        }
        __syncthreads();

        // ========= coalesced store with bias ================================
#pragma unroll 2
        for (int rr = 0; rr < 8; rr++) {
            const int r = wid * 8 + rr;
            const int e = m0 + r;
            if (e < E) {
                const float* sp = stage + r * STG_STRIDE + 4 * lid;
                float4 v;
                v.x = sp[0] + bia0;
                v.y = sp[1] + bia1;
                v.z = sp[2] + bia2;
                v.w = sp[3] + bia3;
                *reinterpret_cast<float4*>(out + (size_t)e * 128 + 4 * lid) = v;
            }
        }
        __syncthreads();   // stage free before next tile's A writes
    }
}

// ============================================================================
// Launch
// ============================================================================
extern "C" void kernel_launch(void* const* d_in, const int* in_sizes, int n_in,
                              void* d_out, int out_size) {
    const float* src   = (const float*)d_in[0];   // src_feat   [E,128] f32
    const float* dstf  = (const float*)d_in[1];   // dst_feat   [E,128] f32
    // d_in[2] = dst_ids (unused: seg_start = dst_max_eid - deg + 1)
    const int*   dme   = (const int*)  d_in[3];   // dst_max_eid [E] i32 or i64
    const float* deg   = (const float*)d_in[4];   // dst_deg    [E] f32
    const float* Wself = (const float*)d_in[5];   // [128,128] f32
    const float* bself = (const float*)d_in[6];   // [128] f32
    const float* Wnei  = (const float*)d_in[7];   // [128,128] f32
    const float* bnei  = (const float*)d_in[8];   // [128] f32
    float* out = (float*)d_out;

    const int E = in_sizes[4];
    const int num_tiles = (E + TILE_M - 1) / TILE_M;

    prep_w_kernel<<<32, 256>>>(Wself, Wnei, (const unsigned*)dme, E);

    int sm_count = 148;
    cudaDeviceGetAttribute(&sm_count, cudaDevAttrMultiProcessorCount, 0);
    int grid = OCC * sm_count;
    if (grid > num_tiles) grid = num_tiles;

    cudaFuncSetAttribute(fused_tsage_kernel,
                         cudaFuncAttributeMaxDynamicSharedMemorySize, SMEM_TOTAL);
    fused_tsage_kernel<<<grid, NTHREADS, SMEM_TOTAL>>>(
        src, dstf, dme, deg, bself, bnei, out, E, num_tiles);
}